// round 11
// baseline (speedup 1.0000x reference)
#include <cuda_runtime.h>

#define NQ 10
#define DEPTH 6
#define NF 1024
#define NC 10

typedef unsigned long long u64;

// ---------- f32x2 packed helpers ----------
__device__ __forceinline__ u64 pk(float x, float y) {
    u64 u; asm("mov.b64 %0,{%1,%2};" : "=l"(u) : "f"(x), "f"(y)); return u;
}
__device__ __forceinline__ u64 dup2(float x) { return pk(x, x); }
__device__ __forceinline__ void unpk(u64 u, float& x, float& y) {
    asm("mov.b64 {%0,%1},%2;" : "=f"(x), "=f"(y) : "l"(u));
}
__device__ __forceinline__ u64 fma2(u64 a, u64 b, u64 c) {
    u64 d; asm("fma.rn.f32x2 %0,%1,%2,%3;" : "=l"(d) : "l"(a), "l"(b), "l"(c)); return d;
}
__device__ __forceinline__ u64 mul2(u64 a, u64 b) {
    u64 d; asm("mul.rn.f32x2 %0,%1,%2;" : "=l"(d) : "l"(a), "l"(b)); return d;
}
__device__ __forceinline__ u64 add2(u64 a, u64 b) {
    u64 d; asm("add.rn.f32x2 %0,%1,%2;" : "=l"(d) : "l"(a), "l"(b)); return d;
}
__device__ __forceinline__ u64 neg2(u64 a) { return a ^ 0x8000000080000000ULL; }
__device__ __forceinline__ u64 rot32(u64 v) { return (v >> 32) | (v << 32); }

#define LOMASK 0x00000000FFFFFFFFULL
#define HIMASK 0xFFFFFFFF00000000ULL
#define FULLM 0xffffffffu

__device__ __forceinline__ float lsgn(int lane, int mask, float v) {
    return (__popc(lane & mask) & 1) ? -v : v;
}

// Amplitude index m (10 bits): bits0-4 = lane, bits5-7 = reg r (0..7), bit8 = u64 half,
// bit9 = warp within the 2-warp block. One sample per 64-thread block.
// CNOT ring range R (1..5). Leading lane/lane run fused into one composed shuffle.
template <int R>
__device__ __forceinline__ void cnot_ring(u64 (&sr)[8], u64 (&si)[8], int lane, int wid,
                                          int tid, u64 (*xbuf)[64]) {
    constexpr int K = (R <= 4) ? (5 - R) : 0;
    if (K > 0) {
        int src = lane;
#pragma unroll
        for (int i = K - 1; i >= 0; i--) src ^= ((src >> i) & 1) << (i + R);
#pragma unroll
        for (int r = 0; r < 8; r++) {
            sr[r] = __shfl_sync(FULLM, sr[r], src);
            si[r] = __shfl_sync(FULLM, si[r], src);
        }
    }
#pragma unroll
    for (int i = K; i < NQ; i++) {
        const int c = i;
        const int t = (i + R) % NQ;
        if (c < 5 && t >= 5 && t < 8) {
            // lane ctrl / reg target
            const int tb = 1 << (t - 5);
            bool ctrl = (lane >> c) & 1;
#pragma unroll
            for (int r0 = 0; r0 < 8; r0++)
                if (!(r0 & tb)) {
                    const int r1 = r0 | tb;
                    u64 t0 = sr[r0], t1 = si[r0];
                    sr[r0] = ctrl ? sr[r1] : sr[r0];
                    si[r0] = ctrl ? si[r1] : si[r0];
                    sr[r1] = ctrl ? t0 : sr[r1];
                    si[r1] = ctrl ? t1 : si[r1];
                }
        } else if (c < 5 && t == 8) {
            // lane ctrl / half target
            bool ctrl = (lane >> c) & 1;
#pragma unroll
            for (int r = 0; r < 8; r++) {
                u64 rr = rot32(sr[r]), ri = rot32(si[r]);
                sr[r] = ctrl ? rr : sr[r];
                si[r] = ctrl ? ri : si[r];
            }
        } else if (c < 5 && t == 9) {
            // lane ctrl / warp target: ctrl lanes swap all values across warps
            bool ctrl = (lane >> c) & 1;
            __syncthreads();
            if (ctrl) {
#pragma unroll
                for (int r = 0; r < 8; r++) { xbuf[r][tid] = sr[r]; xbuf[r + 8][tid] = si[r]; }
            }
            __syncthreads();
            if (ctrl) {
                int p = tid ^ 32;
#pragma unroll
                for (int r = 0; r < 8; r++) { sr[r] = xbuf[r][p]; si[r] = xbuf[r + 8][p]; }
            }
        } else if (c >= 5 && c < 8 && t < 5) {
            // reg ctrl / lane target
            const int cb = 1 << (c - 5);
#pragma unroll
            for (int r = 0; r < 8; r++)
                if (r & cb) {
                    sr[r] = __shfl_xor_sync(FULLM, sr[r], 1 << t);
                    si[r] = __shfl_xor_sync(FULLM, si[r], 1 << t);
                }
        } else if (c >= 5 && c < 8 && t >= 5 && t < 8) {
            // reg ctrl / reg target: free rename
            const int cb = 1 << (c - 5), tb = 1 << (t - 5);
#pragma unroll
            for (int r0 = 0; r0 < 8; r0++)
                if ((r0 & cb) && !(r0 & tb)) {
                    const int r1 = r0 | tb;
                    u64 tmp = sr[r0]; sr[r0] = sr[r1]; sr[r1] = tmp;
                    tmp = si[r0]; si[r0] = si[r1]; si[r1] = tmp;
                }
        } else if (c >= 5 && c < 8 && t == 8) {
            // reg ctrl / half target
            const int cb = 1 << (c - 5);
#pragma unroll
            for (int r = 0; r < 8; r++)
                if (r & cb) {
                    sr[r] = rot32(sr[r]);
                    si[r] = rot32(si[r]);
                }
        } else if (c >= 5 && c < 8 && t == 9) {
            // reg ctrl / warp target: controlled regs swap across warps
            const int cb = 1 << (c - 5);
            __syncthreads();
#pragma unroll
            for (int r = 0; r < 8; r++)
                if (r & cb) { xbuf[r][tid] = sr[r]; xbuf[r + 8][tid] = si[r]; }
            __syncthreads();
            {
                int p = tid ^ 32;
#pragma unroll
                for (int r = 0; r < 8; r++)
                    if (r & cb) { sr[r] = xbuf[r][p]; si[r] = xbuf[r + 8][p]; }
            }
        } else if (c == 8 && t < 5) {
            // half ctrl / lane target: shuffle only hi words
#pragma unroll
            for (int r = 0; r < 8; r++) {
                unsigned hr_ = (unsigned)(sr[r] >> 32);
                unsigned hi_ = (unsigned)(si[r] >> 32);
                hr_ = __shfl_xor_sync(FULLM, hr_, 1 << t);
                hi_ = __shfl_xor_sync(FULLM, hi_, 1 << t);
                sr[r] = (sr[r] & LOMASK) | ((u64)hr_ << 32);
                si[r] = (si[r] & LOMASK) | ((u64)hi_ << 32);
            }
        } else if (c == 8 && t >= 5 && t < 8) {
            // half ctrl / reg target: swap hi halves between reg pairs
            const int tb = 1 << (t - 5);
#pragma unroll
            for (int r0 = 0; r0 < 8; r0++)
                if (!(r0 & tb)) {
                    const int r1 = r0 | tb;
                    u64 a = sr[r0], b = sr[r1];
                    sr[r0] = (a & LOMASK) | (b & HIMASK);
                    sr[r1] = (b & LOMASK) | (a & HIMASK);
                    a = si[r0]; b = si[r1];
                    si[r0] = (a & LOMASK) | (b & HIMASK);
                    si[r1] = (b & LOMASK) | (a & HIMASK);
                }
        } else if (c == 8 && t == 9) {
            // half ctrl / warp target: swap hi halves across warps (R=1)
            __syncthreads();
#pragma unroll
            for (int r = 0; r < 8; r++) { xbuf[r][tid] = sr[r]; xbuf[r + 8][tid] = si[r]; }
            __syncthreads();
            {
                int p = tid ^ 32;
#pragma unroll
                for (int r = 0; r < 8; r++) {
                    sr[r] = (sr[r] & LOMASK) | (xbuf[r][p] & HIMASK);
                    si[r] = (si[r] & LOMASK) | (xbuf[r + 8][p] & HIMASK);
                }
            }
        } else {  // c == 9, t < 5: warp ctrl / lane target — warp 1 permutes locally
            if (wid == 1) {
#pragma unroll
                for (int r = 0; r < 8; r++) {
                    sr[r] = __shfl_xor_sync(FULLM, sr[r], 1 << t);
                    si[r] = __shfl_xor_sync(FULLM, si[r], 1 << t);
                }
            }
        }
    }
}

__device__ __forceinline__ float sel10(const float* e, int lane) {
    float v = e[0];
#pragma unroll
    for (int q = 1; q < 10; q++)
        if (lane == q) v = e[q];
    return v;
}

__global__ __launch_bounds__(64, 14) void fused_kernel(
    const float* __restrict__ x, const float* __restrict__ Wp,
    const float* __restrict__ w, const float* __restrict__ Wout,
    const float* __restrict__ bout, float* __restrict__ out) {
    __shared__ u64 xbuf[16][64];          // 8KB cross-warp exchange buffer
    __shared__ float4 srot[DEPTH * NQ];   // SU(2) gates (alpha_r, alpha_i, beta_r, beta_i)
    __shared__ float pbuf[2][NQ];         // projection partials
    __shared__ float ebuf[NQ];            // warp1 expvals

    const int tid = threadIdx.x;
    const int wid = tid >> 5, lane = tid & 31;
    const int b = blockIdx.x;

    if (tid < DEPTH * NQ) {
        float phi = w[tid * 3 + 0], theta = w[tid * 3 + 1], omega = w[tid * 3 + 2];
        float c, s;
        sincosf(0.5f * theta, &s, &c);
        float sp, cp, sm, cm;
        sincosf(-0.5f * (phi + omega), &sp, &cp);
        sincosf(-0.5f * (phi - omega), &sm, &cm);
        srot[tid] = make_float4(cp * c, sp * c, -cm * s, sm * s);
    }

    // ---- projection split across the two warps ----
    float myc = 0.f, mys = 0.f;
    {
        const float4* xv = (const float4*)(x + (size_t)b * NF);
        float acc[NQ];
#pragma unroll
        for (int q = 0; q < NQ; q++) acc[q] = 0.f;
#pragma unroll
        for (int j = 0; j < 4; j++) {
            int it = wid * 4 + j;
            float4 xx = xv[it * 32 + lane];
#pragma unroll
            for (int q = 0; q < NQ; q++) {
                float4 ww = __ldg(&((const float4*)(Wp + q * NF))[it * 32 + lane]);
                acc[q] += xx.x * ww.x + xx.y * ww.y + xx.z * ww.z + xx.w * ww.w;
            }
        }
#pragma unroll
        for (int off = 16; off > 0; off >>= 1)
#pragma unroll
            for (int q = 0; q < NQ; q++) acc[q] += __shfl_xor_sync(FULLM, acc[q], off);
        if (lane < NQ) pbuf[wid][lane] = sel10(acc, lane);
        __syncthreads();
        if (lane < NQ) {
            float v = pbuf[0][lane] + pbuf[1][lane];
            float half = tanhf(v) * 0.78539816339744831f;
            sincosf(half, &mys, &myc);
        }
    }

    // ---- init: RY product state with layer-0 Rot folded in ----
    float plr, pli;
    {
        plr = 1.f; pli = 0.f;
#pragma unroll
        for (int q = 0; q < 5; q++) {
            float cq = __shfl_sync(FULLM, myc, q);
            float sq = __shfl_sync(FULLM, mys, q);
            float4 G = srot[q];
            bool bq = (lane >> q) & 1;
            float wr = bq ? (-G.z * cq + G.x * sq) : (G.x * cq + G.z * sq);
            float wi = bq ? (G.w * cq - G.y * sq) : (G.y * cq + G.w * sq);
            float nr = plr * wr - pli * wi;
            float ni = plr * wi + pli * wr;
            plr = nr; pli = ni;
        }
        // fold q9 (warp bit) factor into the lane product
        float c9 = __shfl_sync(FULLM, myc, 9), s9 = __shfl_sync(FULLM, mys, 9);
        float4 G9 = srot[9];
        float w9r = wid ? (-G9.z * c9 + G9.x * s9) : (G9.x * c9 + G9.z * s9);
        float w9i = wid ? (G9.w * c9 - G9.y * s9) : (G9.y * c9 + G9.w * s9);
        float nr = plr * w9r - pli * w9i;
        float ni = plr * w9i + pli * w9r;
        plr = nr; pli = ni;
    }
    u64 sr[8], si[8];
    {
        float ar2[4], ai2[4], v7r[2], v7i[2];
        {
            float c5 = __shfl_sync(FULLM, myc, 5), s5 = __shfl_sync(FULLM, mys, 5);
            float c6 = __shfl_sync(FULLM, myc, 6), s6 = __shfl_sync(FULLM, mys, 6);
            float c7 = __shfl_sync(FULLM, myc, 7), s7 = __shfl_sync(FULLM, mys, 7);
            float4 G5 = srot[5], G6 = srot[6], G7 = srot[7];
            float v5r[2], v5i[2], v6r[2], v6i[2];
            v5r[0] = G5.x * c5 + G5.z * s5; v5i[0] = G5.y * c5 + G5.w * s5;
            v5r[1] = -G5.z * c5 + G5.x * s5; v5i[1] = G5.w * c5 - G5.y * s5;
            v6r[0] = G6.x * c6 + G6.z * s6; v6i[0] = G6.y * c6 + G6.w * s6;
            v6r[1] = -G6.z * c6 + G6.x * s6; v6i[1] = G6.w * c6 - G6.y * s6;
            v7r[0] = G7.x * c7 + G7.z * s7; v7i[0] = G7.y * c7 + G7.w * s7;
            v7r[1] = -G7.z * c7 + G7.x * s7; v7i[1] = G7.w * c7 - G7.y * s7;
#pragma unroll
            for (int k = 0; k < 4; k++) {
                int b5 = k & 1, b6 = (k >> 1) & 1;
                ar2[k] = v5r[b5] * v6r[b6] - v5i[b5] * v6i[b6];
                ai2[k] = v5r[b5] * v6i[b6] + v5i[b5] * v6r[b6];
            }
        }
        float c8 = __shfl_sync(FULLM, myc, 8), s8 = __shfl_sync(FULLM, mys, 8);
        float4 G8 = srot[8];
        u64 V8r = pk(G8.x * c8 + G8.z * s8, -G8.z * c8 + G8.x * s8);
        u64 V8i = pk(G8.y * c8 + G8.w * s8, G8.w * c8 - G8.y * s8);
#pragma unroll
        for (int r = 0; r < 8; r++) {
            float lr = ar2[r & 3], li = ai2[r & 3];
            float hr = v7r[r >> 2], hi = v7i[r >> 2];
            float rpr = lr * hr - li * hi;
            float rpi = lr * hi + li * hr;
            float baser = plr * rpr - pli * rpi;
            float basei = plr * rpi + pli * rpr;
            u64 br_ = dup2(baser), bi_ = dup2(basei);
            sr[r] = fma2(br_, V8r, mul2(neg2(bi_), V8i));
            si[r] = fma2(br_, V8i, mul2(bi_, V8r));
        }
    }

    // ---- layer 0 entangler, then layers 1..5 ----
    cnot_ring<1>(sr, si, lane, wid, tid, xbuf);
#pragma unroll 1
    for (int l = 1; l < DEPTH; l++) {
        // lane gates q0..q4
#pragma unroll
        for (int q = 0; q < 5; q++) {
            float4 G = srot[l * NQ + q];
            bool hi = (lane >> q) & 1;
            float sai = hi ? -G.y : G.y;
            float sbr = hi ? -G.z : G.z;
            u64 Ar = dup2(G.x), Sai = dup2(sai), Sain = dup2(-sai);
            u64 Sbr = dup2(sbr), Bi = dup2(G.w), Bin = dup2(-G.w);
#pragma unroll
            for (int r = 0; r < 8; r++) {
                u64 pr_ = __shfl_xor_sync(FULLM, sr[r], 1 << q);
                u64 pi_ = __shfl_xor_sync(FULLM, si[r], 1 << q);
                u64 mr = sr[r], mi = si[r];
                u64 t;
                t = mul2(Bin, pi_); t = fma2(Sbr, pr_, t); t = fma2(Sain, mi, t);
                sr[r] = fma2(Ar, mr, t);
                t = mul2(Bi, pr_); t = fma2(Sbr, pi_, t); t = fma2(Sai, mr, t);
                si[r] = fma2(Ar, mi, t);
            }
        }
        // reg gates q5..q7
#pragma unroll
        for (int q = 5; q < 8; q++) {
            float4 G = srot[l * NQ + q];
            u64 Ar = dup2(G.x), Ai = dup2(G.y), Ain = dup2(-G.y);
            u64 Br = dup2(G.z), Brn = dup2(-G.z);
            u64 Bi = dup2(G.w), Bin = dup2(-G.w);
            const int jb = 1 << (q - 5);
#pragma unroll
            for (int r0 = 0; r0 < 8; r0++)
                if (!(r0 & jb)) {
                    const int r1 = r0 | jb;
                    u64 a0r = sr[r0], a0i = si[r0];
                    u64 a1r = sr[r1], a1i = si[r1];
                    u64 t;
                    t = mul2(Bin, a1i); t = fma2(Br, a1r, t); t = fma2(Ain, a0i, t);
                    sr[r0] = fma2(Ar, a0r, t);
                    t = mul2(Bi, a1r); t = fma2(Br, a1i, t); t = fma2(Ai, a0r, t);
                    si[r0] = fma2(Ar, a0i, t);
                    t = mul2(Bin, a0i); t = fma2(Brn, a0r, t); t = fma2(Ai, a1i, t);
                    sr[r1] = fma2(Ar, a1r, t);
                    t = mul2(Bi, a0r); t = fma2(Brn, a0i, t); t = fma2(Ain, a1r, t);
                    si[r1] = fma2(Ar, a1i, t);
                }
        }
        // half gate q8
        {
            float4 G = srot[l * NQ + 8];
            u64 K0r = dup2(G.x), K0i = pk(G.y, -G.y), K0in = pk(-G.y, G.y);
            u64 K1r = pk(G.z, -G.z), K1i = dup2(G.w), K1in = dup2(-G.w);
#pragma unroll
            for (int r = 0; r < 8; r++) {
                u64 mr = sr[r], mi = si[r];
                u64 tr = rot32(mr), ti = rot32(mi);
                u64 t;
                t = mul2(K1in, ti); t = fma2(K1r, tr, t); t = fma2(K0in, mi, t);
                sr[r] = fma2(K0r, mr, t);
                t = mul2(K1i, tr); t = fma2(K1r, ti, t); t = fma2(K0i, mr, t);
                si[r] = fma2(K0r, mi, t);
            }
        }
        // warp gate q9: exchange + per-warp coefficients
        {
            float4 G = srot[l * NQ + 9];
            float oai = wid ? -G.y : G.y;   // own coef = alpha (w0) / conj(alpha) (w1)
            float obr = wid ? -G.z : G.z;   // partner coef = beta (w0) / -conj(beta) (w1)
            u64 COr = dup2(G.x), COi = dup2(oai), COin = dup2(-oai);
            u64 CPr = dup2(obr), CPi = dup2(G.w), CPin = dup2(-G.w);
            __syncthreads();
#pragma unroll
            for (int r = 0; r < 8; r++) { xbuf[r][tid] = sr[r]; xbuf[r + 8][tid] = si[r]; }
            __syncthreads();
            int p = tid ^ 32;
#pragma unroll
            for (int r = 0; r < 8; r++) {
                u64 pr_ = xbuf[r][p], pi_ = xbuf[r + 8][p];
                u64 mr = sr[r], mi = si[r];
                u64 t;
                t = mul2(CPin, pi_); t = fma2(CPr, pr_, t); t = fma2(COin, mi, t);
                sr[r] = fma2(COr, mr, t);
                t = mul2(CPi, pr_); t = fma2(CPr, pi_, t); t = fma2(COi, mr, t);
                si[r] = fma2(COr, mi, t);
            }
        }
        switch (l) {
            case 1: cnot_ring<2>(sr, si, lane, wid, tid, xbuf); break;
            case 2: cnot_ring<3>(sr, si, lane, wid, tid, xbuf); break;
            case 3: cnot_ring<4>(sr, si, lane, wid, tid, xbuf); break;
            case 4: cnot_ring<5>(sr, si, lane, wid, tid, xbuf); break;
            default: break;  // layer 5's R=6 ring folded into expvals
        }
    }

    // ---- Z expvals with R=6 ring folded in (masks over qubit bits) ----
    // m0={0,4} m1={1,5} m2={0,2,6} m3={1,3,7} m4={2,4,8} m5={3,5,9}
    // m6={0,6} m7={1,7} m8={2,8} m9={3,9};  q5-7=reg bits, q8=half, q9=warp
    u64 A0 = 0ULL, A1 = 0ULL, A2 = 0ULL, A4 = 0ULL;
#pragma unroll
    for (int r = 0; r < 8; r++) {
        u64 p = fma2(sr[r], sr[r], mul2(si[r], si[r]));
        u64 np = neg2(p);
        A0 = add2(A0, p);
        A1 = add2(A1, (r & 1) ? np : p);
        A2 = add2(A2, (r & 2) ? np : p);
        A4 = add2(A4, (r & 4) ? np : p);
    }
    float e[NQ];
    {
        float lo, hi;
        unpk(A0, lo, hi);
        e[0] = lsgn(lane, 0x11, lo + hi);
        e[4] = lsgn(lane, 0x14, lo - hi);
        e[8] = lsgn(lane, 0x04, lo - hi);
        e[9] = lsgn(lane, 0x08, lo + hi);   // warp-diff
        unpk(A1, lo, hi);
        e[1] = lsgn(lane, 0x02, lo + hi);
        e[5] = lsgn(lane, 0x08, lo + hi);   // warp-diff
        unpk(A2, lo, hi);
        e[2] = lsgn(lane, 0x05, lo + hi);
        e[6] = lsgn(lane, 0x01, lo + hi);
        unpk(A4, lo, hi);
        e[3] = lsgn(lane, 0x0A, lo + hi);
        e[7] = lsgn(lane, 0x02, lo + hi);
    }
    u64 E[5];
#pragma unroll
    for (int k = 0; k < 5; k++) E[k] = pk(e[2 * k], e[2 * k + 1]);
#pragma unroll
    for (int off = 16; off > 0; off >>= 1)
#pragma unroll
        for (int k = 0; k < 5; k++)
            E[k] = add2(E[k], __shfl_xor_sync(FULLM, E[k], off));
#pragma unroll
    for (int k = 0; k < 5; k++) unpk(E[k], e[2 * k], e[2 * k + 1]);

    // cross-warp combine: sum for all q except {5,9} which are differences (w0 - w1)
    __syncthreads();
    if (wid == 1 && lane < NQ) ebuf[lane] = sel10(e, lane);
    __syncthreads();
    if (wid == 0 && lane < NC) {
        float mine = sel10(e, lane);
        float other = ebuf[lane];
        float eq = (lane == 5 || lane == 9) ? (mine - other) : (mine + other);
        // gather all 10 combined expvals via shfl after recomputing per-lane value
        // (each lane<10 holds combined e for its own q; head needs all 10 -> share)
        float o = __ldg(&bout[lane]);
#pragma unroll
        for (int q = 0; q < NQ; q++) {
            float ev = __shfl_sync(0x3ffu, eq, q);
            o += ev * __ldg(&Wout[lane * NQ + q]);
        }
        out[(size_t)b * NC + lane] = o;
    }
}

extern "C" void kernel_launch(void* const* d_in, const int* in_sizes, int n_in,
                              void* d_out, int out_size) {
    const float* x = (const float*)d_in[0];        // (B, 1024)
    const float* W_proj = (const float*)d_in[1];   // (10, 1024)
    const float* weights = (const float*)d_in[2];  // (6, 10, 3)
    const float* W_out = (const float*)d_in[3];    // (10, 10)
    const float* b_out = (const float*)d_in[4];    // (10,)
    float* out = (float*)d_out;                    // (B, 10)

    int B = in_sizes[0] / NF;
    fused_kernel<<<B, 64>>>(x, W_proj, weights, W_out, b_out, out);
}